// round 12
// baseline (speedup 1.0000x reference)
#include <cuda_runtime.h>
#include <math.h>

#define BB   256   // batch
#define CC   256   // channels
#define TT   256   // tokens (16x16)
#define NH   8
#define HD   32
#define META 256
#define OC3  768

// ---------------- scratch (device globals; no runtime allocation) ----------
__device__ float g_q[(size_t)BB * NH * TT * HD];     // [b][h][t][d] (raw)
__device__ float g_k[(size_t)BB * NH * TT * HD];     // [b][h][t][d] (raw)
__device__ float g_v[(size_t)BB * NH * TT * HD];
__device__ float g_ao[(size_t)BB * CC * TT];         // [b][c][t]
__device__ float g_biasT[(size_t)NH * TT * TT];      // [h][key][query]
__device__ float g_biasMax[NH * TT];                 // max over key, per (h,query)

// ---------------------------------------------------------------------------
// Kernel 1: relative-position-bias MLP (transposed store: [h][key][query])
// ---------------------------------------------------------------------------
__global__ __launch_bounds__(256) void bias_kernel(
    const float* __restrict__ mw1, const float* __restrict__ mb1,
    const float* __restrict__ mw2, const float* __restrict__ mb2)
{
    __shared__ float s_w1[META * 2];
    __shared__ float s_b1[META];
    __shared__ float s_w2[NH * META];
    __shared__ float s_b2[NH];
    for (int i = threadIdx.x; i < META * 2; i += 256) s_w1[i] = mw1[i];
    for (int i = threadIdx.x; i < META;     i += 256) s_b1[i] = mb1[i];
    for (int i = threadIdx.x; i < NH * META; i += 256) s_w2[i] = mw2[i];
    if (threadIdx.x < NH) s_b2[threadIdx.x] = mb2[threadIdx.x];
    __syncthreads();

    int idx = blockIdx.x * 256 + threadIdx.x;   // idx = key*T + q  (q fast)
    int q  = idx & (TT - 1);
    int kk = idx >> 8;

    float d0 = (float)((q >> 4) - (kk >> 4));
    float d1 = (float)((q & 15) - (kk & 15));
    float r0 = copysignf(log1pf(fabsf(d0)), d0);
    float r1 = copysignf(log1pf(fabsf(d1)), d1);

    float acc[NH];
#pragma unroll
    for (int h = 0; h < NH; h++) acc[h] = s_b2[h];

    for (int j = 0; j < META; j++) {
        float hj = fmaf(r0, s_w1[2 * j], fmaf(r1, s_w1[2 * j + 1], s_b1[j]));
        hj = fmaxf(hj, 0.0f);
#pragma unroll
        for (int h = 0; h < NH; h++)
            acc[h] = fmaf(hj, s_w2[h * META + j], acc[h]);
    }
#pragma unroll
    for (int h = 0; h < NH; h++)
        g_biasT[(size_t)h * TT * TT + (size_t)kk * TT + q] = acc[h];
}

// Kernel 1b: per-(h,q) max over keys of the bias table.
__global__ __launch_bounds__(256) void biasmax_kernel()
{
    int h = blockIdx.x;
    int q = threadIdx.x;
    const float* p = g_biasT + (size_t)h * TT * TT + q;
    float m = -1e30f;
#pragma unroll 8
    for (int k = 0; k < TT; k++)
        m = fmaxf(m, p[(size_t)k * TT]);
    g_biasMax[h * TT + q] = m;
}

// ---------------------------------------------------------------------------
// GEMM tiles: 128(m) x 128(n) x 16(k), 256 threads, 8x8 micro-tile  (R6 ver.)
// ---------------------------------------------------------------------------
#define GBM 128
#define GBN 128
#define GBK 16
#define BNP 132

// Kernel 2: QKV GEMM.  qkv[b,t,oc] = sum_c x[b,c,t] * w[oc,c] + b[oc]
__global__ __launch_bounds__(256, 2) void qkv_kernel(
    const float* __restrict__ x, const float* __restrict__ w,
    const float* __restrict__ bq)
{
    __shared__ float As[GBK * GBM];   // [k][m]
    __shared__ float Bs[GBK * BNP];   // [k][n+pad]

    const int tid = threadIdx.x;
    const int tx = tid & 15;
    const int ty = tid >> 4;
    const int m0 = blockIdx.y * GBM;
    const int n0 = blockIdx.x * GBN;
    const int b  = m0 >> 8;
    const int t0 = m0 & (TT - 1);
    const float* xb = x + (size_t)b * CC * TT;

    float acc[8][8];
#pragma unroll
    for (int i = 0; i < 8; i++)
#pragma unroll
        for (int j = 0; j < 8; j++) acc[i][j] = 0.0f;

    for (int k0 = 0; k0 < CC; k0 += GBK) {
#pragma unroll
        for (int s = 0; s < 2; s++) {
            int item = tid + s * 256;
            int kk = item >> 5;
            int t4 = item & 31;
            float4 v4 = *(const float4*)(xb + (size_t)(k0 + kk) * TT + t0 + t4 * 4);
            *(float4*)(As + kk * GBM + t4 * 4) = v4;
        }
#pragma unroll
        for (int s = 0; s < 2; s++) {
            int item = tid + s * 256;
            int n  = item >> 2;
            int kq = item & 3;
            float4 v4 = *(const float4*)(w + (size_t)(n0 + n) * CC + k0 + kq * 4);
            Bs[(kq * 4 + 0) * BNP + n] = v4.x;
            Bs[(kq * 4 + 1) * BNP + n] = v4.y;
            Bs[(kq * 4 + 2) * BNP + n] = v4.z;
            Bs[(kq * 4 + 3) * BNP + n] = v4.w;
        }
        __syncthreads();

#pragma unroll
        for (int k = 0; k < GBK; k++) {
            float4 a0 = *(const float4*)(As + k * GBM + tx * 4);
            float4 a1 = *(const float4*)(As + k * GBM + tx * 4 + 64);
            float4 b0 = *(const float4*)(Bs + k * BNP + ty * 4);
            float4 b1 = *(const float4*)(Bs + k * BNP + ty * 4 + 64);
            float ar[8] = {a0.x, a0.y, a0.z, a0.w, a1.x, a1.y, a1.z, a1.w};
            float br[8] = {b0.x, b0.y, b0.z, b0.w, b1.x, b1.y, b1.z, b1.w};
#pragma unroll
            for (int i = 0; i < 8; i++)
#pragma unroll
                for (int j = 0; j < 8; j++)
                    acc[i][j] = fmaf(ar[i], br[j], acc[i][j]);
        }
        __syncthreads();
    }

#pragma unroll
    for (int g = 0; g < 2; g++) {
        const int oc0 = n0 + ty * 4 + g * 64;
        const int s   = oc0 >> 8;                 // 0=q 1=k 2=v
        const int ch  = oc0 & (CC - 1);
        const int h   = ch >> 5;
        const int d0  = ch & (HD - 1);
        float4 bb = *(const float4*)(bq + oc0);
        float* dst = ((s == 0) ? g_q : (s == 1) ? g_k : g_v)
                   + (((size_t)b * NH + h) * TT) * HD + d0;
#pragma unroll
        for (int i = 0; i < 8; i++) {
            int t = t0 + tx * 4 + (i >> 2) * 64 + (i & 3);
            float4 o;
            o.x = acc[i][g * 4 + 0] + bb.x;
            o.y = acc[i][g * 4 + 1] + bb.y;
            o.z = acc[i][g * 4 + 2] + bb.z;
            o.w = acc[i][g * 4 + 3] + bb.w;
            *(float4*)(dst + (size_t)t * HD) = o;
        }
    }
}

// ---------------------------------------------------------------------------
// Kernel 3: attention, branch-free fixed-shift softmax, fused normalization.
// One block per (b,h); 128 threads, 2 queries/thread; K/V staged 64 keys.
// q scaled in registers by rsqrt(|q|^2)/tau; k norms in smem table (once).
// e = exp(dot * ikn[key] + bias - M),  M = biasMax + 1/tau >= score.
// ---------------------------------------------------------------------------
#define KSTAGE 64
#define KP     36

__global__ __launch_bounds__(128, 3) void attn_kernel(const float* __restrict__ tau)
{
    __shared__ float ks[KSTAGE * KP];
    __shared__ float vs[KSTAGE * KP];
    __shared__ float ikn_s[TT];

    const int tid = threadIdx.x;
    const int bh  = blockIdx.x;
    const int b   = bh >> 3;
    const int h   = bh & 7;
    const size_t base = (size_t)bh * TT * HD;
    const float inv_tau = 1.0f / fmaxf(tau[h], 0.01f);

    // ---- k-norm table (once per block): 2 keys per thread
#pragma unroll
    for (int r = 0; r < 2; r++) {
        int key = tid + r * 128;
        const float4* kr = (const float4*)(g_k + base + (size_t)key * HD);
        float s2 = 0.0f;
#pragma unroll
        for (int i = 0; i < 8; i++) {
            float4 t4 = kr[i];
            s2 = fmaf(t4.x, t4.x, s2);
            s2 = fmaf(t4.y, t4.y, s2);
            s2 = fmaf(t4.z, t4.z, s2);
            s2 = fmaf(t4.w, t4.w, s2);
        }
        ikn_s[key] = rsqrtf(fmaxf(s2, 1e-12f));
    }

    // ---- own 2 query rows -> registers, normalized by rsqrt(|q|^2)*inv_tau
    float q0[HD], q1[HD], a0[HD], a1[HD];
    {
        const float4* qr0 = (const float4*)(g_q + base + (size_t)tid * HD);
        const float4* qr1 = (const float4*)(g_q + base + (size_t)(tid + 128) * HD);
        float s0 = 0.0f, s1 = 0.0f;
#pragma unroll
        for (int i = 0; i < 8; i++) {
            float4 t4 = qr0[i];
            q0[4*i+0] = t4.x; q0[4*i+1] = t4.y; q0[4*i+2] = t4.z; q0[4*i+3] = t4.w;
            s0 = fmaf(t4.x, t4.x, s0); s0 = fmaf(t4.y, t4.y, s0);
            s0 = fmaf(t4.z, t4.z, s0); s0 = fmaf(t4.w, t4.w, s0);
            float4 u4 = qr1[i];
            q1[4*i+0] = u4.x; q1[4*i+1] = u4.y; q1[4*i+2] = u4.z; q1[4*i+3] = u4.w;
            s1 = fmaf(u4.x, u4.x, s1); s1 = fmaf(u4.y, u4.y, s1);
            s1 = fmaf(u4.z, u4.z, s1); s1 = fmaf(u4.w, u4.w, s1);
        }
        float sc0 = rsqrtf(fmaxf(s0, 1e-12f)) * inv_tau;
        float sc1 = rsqrtf(fmaxf(s1, 1e-12f)) * inv_tau;
#pragma unroll
        for (int d = 0; d < HD; d++) { q0[d] *= sc0; q1[d] *= sc1; }
    }
#pragma unroll
    for (int d = 0; d < HD; d++) { a0[d] = 0.0f; a1[d] = 0.0f; }

    const float M0 = g_biasMax[h * TT + tid]       + inv_tau;
    const float M1 = g_biasMax[h * TT + tid + 128] + inv_tau;
    const float* brow0 = g_biasT + (size_t)h * TT * TT + tid;
    const float* brow1 = brow0 + 128;

    float l0 = 0.0f, l1 = 0.0f;

    for (int j0 = 0; j0 < TT; j0 += KSTAGE) {
        __syncthreads();
        const float4* kg4 = (const float4*)(g_k + base + (size_t)j0 * HD);
        const float4* vg4 = (const float4*)(g_v + base + (size_t)j0 * HD);
#pragma unroll
        for (int it = 0; it < 4; it++) {
            int i = tid + it * 128;
            int r = i >> 3, c = i & 7;
            *(float4*)(ks + r * KP + c * 4) = kg4[i];
            *(float4*)(vs + r * KP + c * 4) = vg4[i];
        }
        __syncthreads();

#pragma unroll 2
        for (int j = 0; j < KSTAGE; j++) {
            const float4* kr = (const float4*)(ks + j * KP);
            float p00 = 0.f, p01 = 0.f, p02 = 0.f, p03 = 0.f;
            float p10 = 0.f, p11 = 0.f, p12 = 0.f, p13 = 0.f;
#pragma unroll
            for (int d4 = 0; d4 < 8; d4++) {
                float4 kv = kr[d4];
                p00 = fmaf(q0[4*d4+0], kv.x, p00);
                p01 = fmaf(q0[4*d4+1], kv.y, p01);
                p02 = fmaf(q0[4*d4+2], kv.z, p02);
                p03 = fmaf(q0[4*d4+3], kv.w, p03);
                p10 = fmaf(q1[4*d4+0], kv.x, p10);
                p11 = fmaf(q1[4*d4+1], kv.y, p11);
                p12 = fmaf(q1[4*d4+2], kv.z, p12);
                p13 = fmaf(q1[4*d4+3], kv.w, p13);
            }
            float ik = ikn_s[j0 + j];
            float bias0 = brow0[(size_t)(j0 + j) * TT];
            float bias1 = brow1[(size_t)(j0 + j) * TT];
            float e0 = __expf(fmaf((p00 + p01) + (p02 + p03), ik, bias0 - M0));
            float e1 = __expf(fmaf((p10 + p11) + (p12 + p13), ik, bias1 - M1));
            l0 += e0;
            l1 += e1;

            const float4* vr = (const float4*)(vs + j * KP);
#pragma unroll
            for (int d4 = 0; d4 < 8; d4++) {
                float4 vv = vr[d4];
                a0[4*d4+0] = fmaf(e0, vv.x, a0[4*d4+0]);
                a0[4*d4+1] = fmaf(e0, vv.y, a0[4*d4+1]);
                a0[4*d4+2] = fmaf(e0, vv.z, a0[4*d4+2]);
                a0[4*d4+3] = fmaf(e0, vv.w, a0[4*d4+3]);
                a1[4*d4+0] = fmaf(e1, vv.x, a1[4*d4+0]);
                a1[4*d4+1] = fmaf(e1, vv.y, a1[4*d4+1]);
                a1[4*d4+2] = fmaf(e1, vv.z, a1[4*d4+2]);
                a1[4*d4+3] = fmaf(e1, vv.w, a1[4*d4+3]);
            }
        }
    }

    const float il0 = 1.0f / l0;
    const float il1 = 1.0f / l1;
    float* ob0 = g_ao + ((size_t)b * CC + h * HD) * TT + tid;
    float* ob1 = ob0 + 128;
#pragma unroll
    for (int d = 0; d < HD; d++) {
        ob0[(size_t)d * TT] = a0[d] * il0;
        ob1[(size_t)d * TT] = a1[d] * il1;
    }
}

// ---------------------------------------------------------------------------
// Kernel 4: proj GEMM.  out[b,co,t] = sum_ci ao[b,ci,t]*w[co,ci] + b[co]  (R6)
// ---------------------------------------------------------------------------
__global__ __launch_bounds__(256, 2) void proj_kernel(
    const float* __restrict__ w, const float* __restrict__ bp,
    float* __restrict__ out)
{
    __shared__ float As[GBK * GBM];
    __shared__ float Bs[GBK * BNP];

    const int tid = threadIdx.x;
    const int tx = tid & 15;
    const int ty = tid >> 4;
    const int m0 = blockIdx.y * GBM;
    const int n0 = blockIdx.x * GBN;
    const int b  = m0 >> 8;
    const int t0 = m0 & (TT - 1);
    const float* ab = g_ao + (size_t)b * CC * TT;

    float acc[8][8];
#pragma unroll
    for (int i = 0; i < 8; i++)
#pragma unroll
        for (int j = 0; j < 8; j++) acc[i][j] = 0.0f;

    for (int k0 = 0; k0 < CC; k0 += GBK) {
#pragma unroll
        for (int s = 0; s < 2; s++) {
            int item = tid + s * 256;
            int kk = item >> 5;
            int t4 = item & 31;
            float4 v4 = *(const float4*)(ab + (size_t)(k0 + kk) * TT + t0 + t4 * 4);
            *(float4*)(As + kk * GBM + t4 * 4) = v4;
        }
#pragma unroll
        for (int s = 0; s < 2; s++) {
            int item = tid + s * 256;
            int n  = item >> 2;
            int kq = item & 3;
            float4 v4 = *(const float4*)(w + (size_t)(n0 + n) * CC + k0 + kq * 4);
            Bs[(kq * 4 + 0) * BNP + n] = v4.x;
            Bs[(kq * 4 + 1) * BNP + n] = v4.y;
            Bs[(kq * 4 + 2) * BNP + n] = v4.z;
            Bs[(kq * 4 + 3) * BNP + n] = v4.w;
        }
        __syncthreads();

#pragma unroll
        for (int k = 0; k < GBK; k++) {
            float4 a0 = *(const float4*)(As + k * GBM + tx * 4);
            float4 a1 = *(const float4*)(As + k * GBM + tx * 4 + 64);
            float4 b0 = *(const float4*)(Bs + k * BNP + ty * 4);
            float4 b1 = *(const float4*)(Bs + k * BNP + ty * 4 + 64);
            float ar[8] = {a0.x, a0.y, a0.z, a0.w, a1.x, a1.y, a1.z, a1.w};
            float br[8] = {b0.x, b0.y, b0.z, b0.w, b1.x, b1.y, b1.z, b1.w};
#pragma unroll
            for (int i = 0; i < 8; i++)
#pragma unroll
                for (int j = 0; j < 8; j++)
                    acc[i][j] = fmaf(ar[i], br[j], acc[i][j]);
        }
        __syncthreads();
    }

#pragma unroll
    for (int g = 0; g < 2; g++) {
#pragma unroll
        for (int j = 0; j < 4; j++) {
            int n = n0 + ty * 4 + g * 64 + j;
            float bpv = bp[n];
            float4 o;
            o.x = acc[0][g*4+j] + bpv;
            o.y = acc[1][g*4+j] + bpv;
            o.z = acc[2][g*4+j] + bpv;
            o.w = acc[3][g*4+j] + bpv;
            *(float4*)(out + ((size_t)b * CC + n) * TT + t0 + tx * 4) = o;
            o.x = acc[4][g*4+j] + bpv;
            o.y = acc[5][g*4+j] + bpv;
            o.z = acc[6][g*4+j] + bpv;
            o.w = acc[7][g*4+j] + bpv;
            *(float4*)(out + ((size_t)b * CC + n) * TT + t0 + tx * 4 + 64) = o;
        }
    }
}

// ---------------------------------------------------------------------------
extern "C" void kernel_launch(void* const* d_in, const int* in_sizes, int n_in,
                              void* d_out, int out_size)
{
    const float* x      = (const float*)d_in[0];
    const float* w_qkv  = (const float*)d_in[1];
    const float* b_qkv  = (const float*)d_in[2];
    const float* w_proj = (const float*)d_in[3];
    const float* b_proj = (const float*)d_in[4];
    const float* mw1    = (const float*)d_in[5];
    const float* mb1    = (const float*)d_in[6];
    const float* mw2    = (const float*)d_in[7];
    const float* mb2    = (const float*)d_in[8];
    const float* tau    = (const float*)d_in[9];
    float* out = (float*)d_out;

    bias_kernel<<<TT * TT / 256, 256>>>(mw1, mb1, mw2, mb2);
    biasmax_kernel<<<NH, 256>>>();
    qkv_kernel<<<dim3(OC3 / GBN, BB * TT / GBM), 256>>>(x, w_qkv, b_qkv);
    attn_kernel<<<BB * NH, 128>>>(tau);
    proj_kernel<<<dim3(CC / GBN, BB * TT / GBM), 256>>>(w_proj, b_proj, out);
}

// round 16
// speedup vs baseline: 1.0183x; 1.0183x over previous
#include <cuda_runtime.h>
#include <math.h>

#define BB   256   // batch
#define CC   256   // channels
#define TT   256   // tokens (16x16)
#define NH   8
#define HD   32
#define META 256
#define OC3  768

typedef unsigned long long u64;

// ---- packed f32x2 helpers (Blackwell FFMA2 path) --------------------------
__device__ __forceinline__ u64 pack2(float lo, float hi) {
    u64 r; asm("mov.b64 %0, {%1, %2};" : "=l"(r) : "f"(lo), "f"(hi)); return r;
}
__device__ __forceinline__ void unpack2(u64 v, float& lo, float& hi) {
    asm("mov.b64 {%0, %1}, %2;" : "=f"(lo), "=f"(hi) : "l"(v));
}
#define FMA2(d, a, b) \
    asm("fma.rn.f32x2 %0, %1, %2, %0;" : "+l"(d) : "l"(a), "l"(b))

// ---------------- scratch (device globals; no runtime allocation) ----------
__device__ float g_q[(size_t)BB * NH * TT * HD];     // [b][h][t][d] (raw)
__device__ float g_k[(size_t)BB * NH * TT * HD];     // [b][h][t][d] (raw)
__device__ float g_v[(size_t)BB * NH * TT * HD];
__device__ float g_ao[(size_t)BB * CC * TT];         // [b][c][t]
__device__ float g_biasT[(size_t)NH * TT * TT];      // [h][key][query]
__device__ float g_biasMax[NH * TT];                 // max over key, per (h,query)

// ---------------------------------------------------------------------------
// Kernel 1: relative-position-bias MLP (transposed store: [h][key][query])
// ---------------------------------------------------------------------------
__global__ __launch_bounds__(256) void bias_kernel(
    const float* __restrict__ mw1, const float* __restrict__ mb1,
    const float* __restrict__ mw2, const float* __restrict__ mb2)
{
    __shared__ float s_w1[META * 2];
    __shared__ float s_b1[META];
    __shared__ float s_w2[NH * META];
    __shared__ float s_b2[NH];
    for (int i = threadIdx.x; i < META * 2; i += 256) s_w1[i] = mw1[i];
    for (int i = threadIdx.x; i < META;     i += 256) s_b1[i] = mb1[i];
    for (int i = threadIdx.x; i < NH * META; i += 256) s_w2[i] = mw2[i];
    if (threadIdx.x < NH) s_b2[threadIdx.x] = mb2[threadIdx.x];
    __syncthreads();

    int idx = blockIdx.x * 256 + threadIdx.x;   // idx = key*T + q  (q fast)
    int q  = idx & (TT - 1);
    int kk = idx >> 8;

    float d0 = (float)((q >> 4) - (kk >> 4));
    float d1 = (float)((q & 15) - (kk & 15));
    float r0 = copysignf(log1pf(fabsf(d0)), d0);
    float r1 = copysignf(log1pf(fabsf(d1)), d1);

    float acc[NH];
#pragma unroll
    for (int h = 0; h < NH; h++) acc[h] = s_b2[h];

    for (int j = 0; j < META; j++) {
        float hj = fmaf(r0, s_w1[2 * j], fmaf(r1, s_w1[2 * j + 1], s_b1[j]));
        hj = fmaxf(hj, 0.0f);
#pragma unroll
        for (int h = 0; h < NH; h++)
            acc[h] = fmaf(hj, s_w2[h * META + j], acc[h]);
    }
#pragma unroll
    for (int h = 0; h < NH; h++)
        g_biasT[(size_t)h * TT * TT + (size_t)kk * TT + q] = acc[h];
}

// Kernel 1b: per-(h,q) max over keys of the bias table.
__global__ __launch_bounds__(256) void biasmax_kernel()
{
    int h = blockIdx.x;
    int q = threadIdx.x;
    const float* p = g_biasT + (size_t)h * TT * TT + q;
    float m = -1e30f;
#pragma unroll 8
    for (int k = 0; k < TT; k++)
        m = fmaxf(m, p[(size_t)k * TT]);
    g_biasMax[h * TT + q] = m;
}

// ---------------------------------------------------------------------------
// GEMM tiles: 128(m) x 128(n) x 16(k), 256 threads, 8x8 micro-tile, FFMA2.
// acc packed along m: acc_p[i2][j] = (acc[2*i2][j], acc[2*i2+1][j]).
// ---------------------------------------------------------------------------
#define GBM 128
#define GBN 128
#define GBK 16
#define BNP 132

// Kernel 2: QKV GEMM.  qkv[b,t,oc] = sum_c x[b,c,t] * w[oc,c] + b[oc]
__global__ __launch_bounds__(256, 2) void qkv_kernel(
    const float* __restrict__ x, const float* __restrict__ w,
    const float* __restrict__ bq)
{
    __shared__ float As[GBK * GBM];   // [k][m]
    __shared__ float Bs[GBK * BNP];   // [k][n+pad]

    const int tid = threadIdx.x;
    const int tx = tid & 15;
    const int ty = tid >> 4;
    const int m0 = blockIdx.y * GBM;
    const int n0 = blockIdx.x * GBN;
    const int b  = m0 >> 8;
    const int t0 = m0 & (TT - 1);
    const float* xb = x + (size_t)b * CC * TT;

    u64 acc_p[4][8];
#pragma unroll
    for (int i = 0; i < 4; i++)
#pragma unroll
        for (int j = 0; j < 8; j++) acc_p[i][j] = 0ull;

    for (int k0 = 0; k0 < CC; k0 += GBK) {
#pragma unroll
        for (int s = 0; s < 2; s++) {
            int item = tid + s * 256;
            int kk = item >> 5;
            int t4 = item & 31;
            float4 v4 = *(const float4*)(xb + (size_t)(k0 + kk) * TT + t0 + t4 * 4);
            *(float4*)(As + kk * GBM + t4 * 4) = v4;
        }
#pragma unroll
        for (int s = 0; s < 2; s++) {
            int item = tid + s * 256;
            int n  = item >> 2;
            int kq = item & 3;
            float4 v4 = *(const float4*)(w + (size_t)(n0 + n) * CC + k0 + kq * 4);
            Bs[(kq * 4 + 0) * BNP + n] = v4.x;
            Bs[(kq * 4 + 1) * BNP + n] = v4.y;
            Bs[(kq * 4 + 2) * BNP + n] = v4.z;
            Bs[(kq * 4 + 3) * BNP + n] = v4.w;
        }
        __syncthreads();

#pragma unroll
        for (int k = 0; k < GBK; k++) {
            const float* arow = As + k * GBM + tx * 4;
            ulonglong2 aa0 = *(const ulonglong2*)(arow);        // rows 0,1 | 2,3
            ulonglong2 aa1 = *(const ulonglong2*)(arow + 64);   // rows 4,5 | 6,7
            float4 b0 = *(const float4*)(Bs + k * BNP + ty * 4);
            float4 b1 = *(const float4*)(Bs + k * BNP + ty * 4 + 64);
            u64 bb[8];
            bb[0] = pack2(b0.x, b0.x); bb[1] = pack2(b0.y, b0.y);
            bb[2] = pack2(b0.z, b0.z); bb[3] = pack2(b0.w, b0.w);
            bb[4] = pack2(b1.x, b1.x); bb[5] = pack2(b1.y, b1.y);
            bb[6] = pack2(b1.z, b1.z); bb[7] = pack2(b1.w, b1.w);
#pragma unroll
            for (int j = 0; j < 8; j++) {
                FMA2(acc_p[0][j], aa0.x, bb[j]);
                FMA2(acc_p[1][j], aa0.y, bb[j]);
                FMA2(acc_p[2][j], aa1.x, bb[j]);
                FMA2(acc_p[3][j], aa1.y, bb[j]);
            }
        }
        __syncthreads();
    }

    // unpack to the old acc[8][8] layout, then old epilogue
    float acc[8][8];
#pragma unroll
    for (int i2 = 0; i2 < 4; i2++)
#pragma unroll
        for (int j = 0; j < 8; j++) {
            float lo, hi;
            unpack2(acc_p[i2][j], lo, hi);
            acc[2 * i2][j] = lo;
            acc[2 * i2 + 1][j] = hi;
        }

#pragma unroll
    for (int g = 0; g < 2; g++) {
        const int oc0 = n0 + ty * 4 + g * 64;
        const int s   = oc0 >> 8;                 // 0=q 1=k 2=v
        const int ch  = oc0 & (CC - 1);
        const int h   = ch >> 5;
        const int d0  = ch & (HD - 1);
        float4 bb = *(const float4*)(bq + oc0);
        float* dst = ((s == 0) ? g_q : (s == 1) ? g_k : g_v)
                   + (((size_t)b * NH + h) * TT) * HD + d0;
#pragma unroll
        for (int i = 0; i < 8; i++) {
            int t = t0 + tx * 4 + (i >> 2) * 64 + (i & 3);
            float4 o;
            o.x = acc[i][g * 4 + 0] + bb.x;
            o.y = acc[i][g * 4 + 1] + bb.y;
            o.z = acc[i][g * 4 + 2] + bb.z;
            o.w = acc[i][g * 4 + 3] + bb.w;
            *(float4*)(dst + (size_t)t * HD) = o;
        }
    }
}

// ---------------------------------------------------------------------------
// Kernel 3: attention, branch-free fixed-shift softmax, fused norm, FFMA2.
// One block per (b,h); 128 threads, 2 queries/thread; K/V staged 64 keys.
// q/acc packed along d (16 f32x2 pairs); K/V pairs free from LDS.128.
// ---------------------------------------------------------------------------
#define KSTAGE 64
#define KP     36

__global__ __launch_bounds__(128, 3) void attn_kernel(const float* __restrict__ tau)
{
    __shared__ float ks[KSTAGE * KP];
    __shared__ float vs[KSTAGE * KP];
    __shared__ float ikn_s[TT];

    const int tid = threadIdx.x;
    const int bh  = blockIdx.x;
    const int b   = bh >> 3;
    const int h   = bh & 7;
    const size_t base = (size_t)bh * TT * HD;
    const float inv_tau = 1.0f / fmaxf(tau[h], 0.01f);

    // ---- k-norm table (once per block): 2 keys per thread
#pragma unroll
    for (int r = 0; r < 2; r++) {
        int key = tid + r * 128;
        const float4* kr = (const float4*)(g_k + base + (size_t)key * HD);
        float s2 = 0.0f;
#pragma unroll
        for (int i = 0; i < 8; i++) {
            float4 t4 = kr[i];
            s2 = fmaf(t4.x, t4.x, s2);
            s2 = fmaf(t4.y, t4.y, s2);
            s2 = fmaf(t4.z, t4.z, s2);
            s2 = fmaf(t4.w, t4.w, s2);
        }
        ikn_s[key] = rsqrtf(fmaxf(s2, 1e-12f));
    }

    // ---- own 2 query rows -> packed registers, scaled by rsqrt(|q|^2)*inv_tau
    u64 q0p[16], q1p[16], a0p[16], a1p[16];
    {
        float q0[HD], q1[HD];
        const float4* qr0 = (const float4*)(g_q + base + (size_t)tid * HD);
        const float4* qr1 = (const float4*)(g_q + base + (size_t)(tid + 128) * HD);
        float s0 = 0.0f, s1 = 0.0f;
#pragma unroll
        for (int i = 0; i < 8; i++) {
            float4 t4 = qr0[i];
            q0[4*i+0] = t4.x; q0[4*i+1] = t4.y; q0[4*i+2] = t4.z; q0[4*i+3] = t4.w;
            s0 = fmaf(t4.x, t4.x, s0); s0 = fmaf(t4.y, t4.y, s0);
            s0 = fmaf(t4.z, t4.z, s0); s0 = fmaf(t4.w, t4.w, s0);
            float4 u4 = qr1[i];
            q1[4*i+0] = u4.x; q1[4*i+1] = u4.y; q1[4*i+2] = u4.z; q1[4*i+3] = u4.w;
            s1 = fmaf(u4.x, u4.x, s1); s1 = fmaf(u4.y, u4.y, s1);
            s1 = fmaf(u4.z, u4.z, s1); s1 = fmaf(u4.w, u4.w, s1);
        }
        float sc0 = rsqrtf(fmaxf(s0, 1e-12f)) * inv_tau;
        float sc1 = rsqrtf(fmaxf(s1, 1e-12f)) * inv_tau;
#pragma unroll
        for (int i = 0; i < 16; i++) {
            q0p[i] = pack2(q0[2*i] * sc0, q0[2*i+1] * sc0);
            q1p[i] = pack2(q1[2*i] * sc1, q1[2*i+1] * sc1);
            a0p[i] = 0ull;
            a1p[i] = 0ull;
        }
    }

    const float M0 = g_biasMax[h * TT + tid]       + inv_tau;
    const float M1 = g_biasMax[h * TT + tid + 128] + inv_tau;
    const float* brow0 = g_biasT + (size_t)h * TT * TT + tid;
    const float* brow1 = brow0 + 128;

    float l0 = 0.0f, l1 = 0.0f;

    for (int j0 = 0; j0 < TT; j0 += KSTAGE) {
        __syncthreads();
        const float4* kg4 = (const float4*)(g_k + base + (size_t)j0 * HD);
        const float4* vg4 = (const float4*)(g_v + base + (size_t)j0 * HD);
#pragma unroll
        for (int it = 0; it < 4; it++) {
            int i = tid + it * 128;
            int r = i >> 3, c = i & 7;
            *(float4*)(ks + r * KP + c * 4) = kg4[i];
            *(float4*)(vs + r * KP + c * 4) = vg4[i];
        }
        __syncthreads();

#pragma unroll 2
        for (int j = 0; j < KSTAGE; j++) {
            const ulonglong2* kp = (const ulonglong2*)(ks + j * KP);
            u64 p0a = 0ull, p0b = 0ull, p1a = 0ull, p1b = 0ull;
#pragma unroll
            for (int i = 0; i < 8; i++) {
                ulonglong2 kk = kp[i];
                FMA2(p0a, q0p[2*i],     kk.x);
                FMA2(p0b, q0p[2*i + 1], kk.y);
                FMA2(p1a, q1p[2*i],     kk.x);
                FMA2(p1b, q1p[2*i + 1], kk.y);
            }
            float x0, y0, x1, y1, u0, v0, u1, v1;
            unpack2(p0a, x0, y0); unpack2(p0b, x1, y1);
            unpack2(p1a, u0, v0); unpack2(p1b, u1, v1);
            float dot0 = (x0 + y0) + (x1 + y1);
            float dot1 = (u0 + v0) + (u1 + v1);

            float ik = ikn_s[j0 + j];
            float bias0 = brow0[(size_t)(j0 + j) * TT];
            float bias1 = brow1[(size_t)(j0 + j) * TT];
            float e0 = __expf(fmaf(dot0, ik, bias0 - M0));
            float e1 = __expf(fmaf(dot1, ik, bias1 - M1));
            l0 += e0;
            l1 += e1;
            u64 ep0 = pack2(e0, e0);
            u64 ep1 = pack2(e1, e1);

            const ulonglong2* vp = (const ulonglong2*)(vs + j * KP);
#pragma unroll
            for (int i = 0; i < 8; i++) {
                ulonglong2 vvp = vp[i];
                FMA2(a0p[2*i],     ep0, vvp.x);
                FMA2(a0p[2*i + 1], ep0, vvp.y);
                FMA2(a1p[2*i],     ep1, vvp.x);
                FMA2(a1p[2*i + 1], ep1, vvp.y);
            }
        }
    }

    const float il0 = 1.0f / l0;
    const float il1 = 1.0f / l1;
    float* ob0 = g_ao + ((size_t)b * CC + h * HD) * TT + tid;
    float* ob1 = ob0 + 128;
#pragma unroll
    for (int i = 0; i < 16; i++) {
        float lo, hi;
        unpack2(a0p[i], lo, hi);
        ob0[(size_t)(2*i) * TT]     = lo * il0;
        ob0[(size_t)(2*i + 1) * TT] = hi * il0;
        unpack2(a1p[i], lo, hi);
        ob1[(size_t)(2*i) * TT]     = lo * il1;
        ob1[(size_t)(2*i + 1) * TT] = hi * il1;
    }
}

// ---------------------------------------------------------------------------
// Kernel 4: proj GEMM, FFMA2.  out[b,co,t] = sum_ci ao[b,ci,t]*w[co,ci]+b[co]
// ---------------------------------------------------------------------------
__global__ __launch_bounds__(256, 2) void proj_kernel(
    const float* __restrict__ w, const float* __restrict__ bp,
    float* __restrict__ out)
{
    __shared__ float As[GBK * GBM];
    __shared__ float Bs[GBK * BNP];

    const int tid = threadIdx.x;
    const int tx = tid & 15;
    const int ty = tid >> 4;
    const int m0 = blockIdx.y * GBM;
    const int n0 = blockIdx.x * GBN;
    const int b  = m0 >> 8;
    const int t0 = m0 & (TT - 1);
    const float* ab = g_ao + (size_t)b * CC * TT;

    u64 acc_p[4][8];
#pragma unroll
    for (int i = 0; i < 4; i++)
#pragma unroll
        for (int j = 0; j < 8; j++) acc_p[i][j] = 0ull;

    for (int k0 = 0; k0 < CC; k0 += GBK) {
#pragma unroll
        for (int s = 0; s < 2; s++) {
            int item = tid + s * 256;
            int kk = item >> 5;
            int t4 = item & 31;
            float4 v4 = *(const float4*)(ab + (size_t)(k0 + kk) * TT + t0 + t4 * 4);
            *(float4*)(As + kk * GBM + t4 * 4) = v4;
        }
#pragma unroll
        for (int s = 0; s < 2; s++) {
            int item = tid + s * 256;
            int n  = item >> 2;
            int kq = item & 3;
            float4 v4 = *(const float4*)(w + (size_t)(n0 + n) * CC + k0 + kq * 4);
            Bs[(kq * 4 + 0) * BNP + n] = v4.x;
            Bs[(kq * 4 + 1) * BNP + n] = v4.y;
            Bs[(kq * 4 + 2) * BNP + n] = v4.z;
            Bs[(kq * 4 + 3) * BNP + n] = v4.w;
        }
        __syncthreads();

#pragma unroll
        for (int k = 0; k < GBK; k++) {
            const float* arow = As + k * GBM + tx * 4;
            ulonglong2 aa0 = *(const ulonglong2*)(arow);
            ulonglong2 aa1 = *(const ulonglong2*)(arow + 64);
            float4 b0 = *(const float4*)(Bs + k * BNP + ty * 4);
            float4 b1 = *(const float4*)(Bs + k * BNP + ty * 4 + 64);
            u64 bb[8];
            bb[0] = pack2(b0.x, b0.x); bb[1] = pack2(b0.y, b0.y);
            bb[2] = pack2(b0.z, b0.z); bb[3] = pack2(b0.w, b0.w);
            bb[4] = pack2(b1.x, b1.x); bb[5] = pack2(b1.y, b1.y);
            bb[6] = pack2(b1.z, b1.z); bb[7] = pack2(b1.w, b1.w);
#pragma unroll
            for (int j = 0; j < 8; j++) {
                FMA2(acc_p[0][j], aa0.x, bb[j]);
                FMA2(acc_p[1][j], aa0.y, bb[j]);
                FMA2(acc_p[2][j], aa1.x, bb[j]);
                FMA2(acc_p[3][j], aa1.y, bb[j]);
            }
        }
        __syncthreads();
    }

    float acc[8][8];
#pragma unroll
    for (int i2 = 0; i2 < 4; i2++)
#pragma unroll
        for (int j = 0; j < 8; j++) {
            float lo, hi;
            unpack2(acc_p[i2][j], lo, hi);
            acc[2 * i2][j] = lo;
            acc[2 * i2 + 1][j] = hi;
        }

#pragma unroll
    for (int g = 0; g < 2; g++) {
#pragma unroll
        for (int j = 0; j < 4; j++) {
            int n = n0 + ty * 4 + g * 64 + j;
            float bpv = bp[n];
            float4 o;
            o.x = acc[0][g*4+j] + bpv;
            o.y = acc[1][g*4+j] + bpv;
            o.z = acc[2][g*4+j] + bpv;
            o.w = acc[3][g*4+j] + bpv;
            *(float4*)(out + ((size_t)b * CC + n) * TT + t0 + tx * 4) = o;
            o.x = acc[4][g*4+j] + bpv;
            o.y = acc[5][g*4+j] + bpv;
            o.z = acc[6][g*4+j] + bpv;
            o.w = acc[7][g*4+j] + bpv;
            *(float4*)(out + ((size_t)b * CC + n) * TT + t0 + tx * 4 + 64) = o;
        }
    }
}

// ---------------------------------------------------------------------------
extern "C" void kernel_launch(void* const* d_in, const int* in_sizes, int n_in,
                              void* d_out, int out_size)
{
    const float* x      = (const float*)d_in[0];
    const float* w_qkv  = (const float*)d_in[1];
    const float* b_qkv  = (const float*)d_in[2];
    const float* w_proj = (const float*)d_in[3];
    const float* b_proj = (const float*)d_in[4];
    const float* mw1    = (const float*)d_in[5];
    const float* mb1    = (const float*)d_in[6];
    const float* mw2    = (const float*)d_in[7];
    const float* mb2    = (const float*)d_in[8];
    const float* tau    = (const float*)d_in[9];
    float* out = (float*)d_out;

    bias_kernel<<<TT * TT / 256, 256>>>(mw1, mb1, mw2, mb2);
    biasmax_kernel<<<NH, 256>>>();
    qkv_kernel<<<dim3(OC3 / GBN, BB * TT / GBM), 256>>>(x, w_qkv, b_qkv);
    attn_kernel<<<BB * NH, 128>>>(tau);
    proj_kernel<<<dim3(CC / GBN, BB * TT / GBM), 256>>>(w_proj, b_proj, out);
}

// round 17
// speedup vs baseline: 1.1572x; 1.1365x over previous
#include <cuda_runtime.h>
#include <math.h>

#define BB   256   // batch
#define CC   256   // channels
#define TT   256   // tokens (16x16)
#define NH   8
#define HD   32
#define META 256
#define OC3  768

typedef unsigned long long u64;

// ---- packed f32x2 helpers (Blackwell FFMA2 path) --------------------------
__device__ __forceinline__ u64 pack2(float lo, float hi) {
    u64 r; asm("mov.b64 %0, {%1, %2};" : "=l"(r) : "f"(lo), "f"(hi)); return r;
}
__device__ __forceinline__ void unpack2(u64 v, float& lo, float& hi) {
    asm("mov.b64 {%0, %1}, %2;" : "=f"(lo), "=f"(hi) : "l"(v));
}
#define FMA2(d, a, b) \
    asm("fma.rn.f32x2 %0, %1, %2, %0;" : "+l"(d) : "l"(a), "l"(b))
#define ADD2(d, a) \
    asm("add.rn.f32x2 %0, %0, %1;" : "+l"(d) : "l"(a))

// ---------------- scratch (device globals; no runtime allocation) ----------
__device__ float g_q[(size_t)BB * NH * TT * HD];     // [b][h][t][d] (raw)
__device__ float g_k[(size_t)BB * NH * TT * HD];     // [b][h][t][d] (raw)
__device__ float g_v[(size_t)BB * NH * TT * HD];
__device__ float g_ao[(size_t)BB * CC * TT];         // [b][c][t]
__device__ float g_biasT[(size_t)NH * TT * TT];      // [h][key][query]
__device__ float g_biasMax[NH * TT];                 // max over key, per (h,query)

// ---------------------------------------------------------------------------
// Kernel 1: relative-position-bias MLP (transposed store: [h][key][query])
// ---------------------------------------------------------------------------
__global__ __launch_bounds__(256) void bias_kernel(
    const float* __restrict__ mw1, const float* __restrict__ mb1,
    const float* __restrict__ mw2, const float* __restrict__ mb2)
{
    __shared__ float s_w1[META * 2];
    __shared__ float s_b1[META];
    __shared__ float s_w2[NH * META];
    __shared__ float s_b2[NH];
    for (int i = threadIdx.x; i < META * 2; i += 256) s_w1[i] = mw1[i];
    for (int i = threadIdx.x; i < META;     i += 256) s_b1[i] = mb1[i];
    for (int i = threadIdx.x; i < NH * META; i += 256) s_w2[i] = mw2[i];
    if (threadIdx.x < NH) s_b2[threadIdx.x] = mb2[threadIdx.x];
    __syncthreads();

    int idx = blockIdx.x * 256 + threadIdx.x;   // idx = key*T + q  (q fast)
    int q  = idx & (TT - 1);
    int kk = idx >> 8;

    float d0 = (float)((q >> 4) - (kk >> 4));
    float d1 = (float)((q & 15) - (kk & 15));
    float r0 = copysignf(log1pf(fabsf(d0)), d0);
    float r1 = copysignf(log1pf(fabsf(d1)), d1);

    float acc[NH];
#pragma unroll
    for (int h = 0; h < NH; h++) acc[h] = s_b2[h];

    for (int j = 0; j < META; j++) {
        float hj = fmaf(r0, s_w1[2 * j], fmaf(r1, s_w1[2 * j + 1], s_b1[j]));
        hj = fmaxf(hj, 0.0f);
#pragma unroll
        for (int h = 0; h < NH; h++)
            acc[h] = fmaf(hj, s_w2[h * META + j], acc[h]);
    }
#pragma unroll
    for (int h = 0; h < NH; h++)
        g_biasT[(size_t)h * TT * TT + (size_t)kk * TT + q] = acc[h];
}

// Kernel 1b: per-(h,q) max over keys of the bias table.
__global__ __launch_bounds__(256) void biasmax_kernel()
{
    int h = blockIdx.x;
    int q = threadIdx.x;
    const float* p = g_biasT + (size_t)h * TT * TT + q;
    float m = -1e30f;
#pragma unroll 8
    for (int k = 0; k < TT; k++)
        m = fmaxf(m, p[(size_t)k * TT]);
    g_biasMax[h * TT + q] = m;
}

// ---------------------------------------------------------------------------
// GEMM tiles: 128(m) x 128(n) x 16(k), 256 threads, 8x8 micro-tile, FFMA2.
// ---------------------------------------------------------------------------
#define GBM 128
#define GBN 128
#define GBK 16
#define BNP 132

// Kernel 2: QKV GEMM.  qkv[b,t,oc] = sum_c x[b,c,t] * w[oc,c] + b[oc]
__global__ __launch_bounds__(256, 2) void qkv_kernel(
    const float* __restrict__ x, const float* __restrict__ w,
    const float* __restrict__ bq)
{
    __shared__ float As[GBK * GBM];   // [k][m]
    __shared__ float Bs[GBK * BNP];   // [k][n+pad]

    const int tid = threadIdx.x;
    const int tx = tid & 15;
    const int ty = tid >> 4;
    const int m0 = blockIdx.y * GBM;
    const int n0 = blockIdx.x * GBN;
    const int b  = m0 >> 8;
    const int t0 = m0 & (TT - 1);
    const float* xb = x + (size_t)b * CC * TT;

    u64 acc_p[4][8];
#pragma unroll
    for (int i = 0; i < 4; i++)
#pragma unroll
        for (int j = 0; j < 8; j++) acc_p[i][j] = 0ull;

    for (int k0 = 0; k0 < CC; k0 += GBK) {
#pragma unroll
        for (int s = 0; s < 2; s++) {
            int item = tid + s * 256;
            int kk = item >> 5;
            int t4 = item & 31;
            float4 v4 = *(const float4*)(xb + (size_t)(k0 + kk) * TT + t0 + t4 * 4);
            *(float4*)(As + kk * GBM + t4 * 4) = v4;
        }
#pragma unroll
        for (int s = 0; s < 2; s++) {
            int item = tid + s * 256;
            int n  = item >> 2;
            int kq = item & 3;
            float4 v4 = *(const float4*)(w + (size_t)(n0 + n) * CC + k0 + kq * 4);
            Bs[(kq * 4 + 0) * BNP + n] = v4.x;
            Bs[(kq * 4 + 1) * BNP + n] = v4.y;
            Bs[(kq * 4 + 2) * BNP + n] = v4.z;
            Bs[(kq * 4 + 3) * BNP + n] = v4.w;
        }
        __syncthreads();

#pragma unroll
        for (int k = 0; k < GBK; k++) {
            const float* arow = As + k * GBM + tx * 4;
            ulonglong2 aa0 = *(const ulonglong2*)(arow);
            ulonglong2 aa1 = *(const ulonglong2*)(arow + 64);
            float4 b0 = *(const float4*)(Bs + k * BNP + ty * 4);
            float4 b1 = *(const float4*)(Bs + k * BNP + ty * 4 + 64);
            u64 bb[8];
            bb[0] = pack2(b0.x, b0.x); bb[1] = pack2(b0.y, b0.y);
            bb[2] = pack2(b0.z, b0.z); bb[3] = pack2(b0.w, b0.w);
            bb[4] = pack2(b1.x, b1.x); bb[5] = pack2(b1.y, b1.y);
            bb[6] = pack2(b1.z, b1.z); bb[7] = pack2(b1.w, b1.w);
#pragma unroll
            for (int j = 0; j < 8; j++) {
                FMA2(acc_p[0][j], aa0.x, bb[j]);
                FMA2(acc_p[1][j], aa0.y, bb[j]);
                FMA2(acc_p[2][j], aa1.x, bb[j]);
                FMA2(acc_p[3][j], aa1.y, bb[j]);
            }
        }
        __syncthreads();
    }

    float acc[8][8];
#pragma unroll
    for (int i2 = 0; i2 < 4; i2++)
#pragma unroll
        for (int j = 0; j < 8; j++) {
            float lo, hi;
            unpack2(acc_p[i2][j], lo, hi);
            acc[2 * i2][j] = lo;
            acc[2 * i2 + 1][j] = hi;
        }

#pragma unroll
    for (int g = 0; g < 2; g++) {
        const int oc0 = n0 + ty * 4 + g * 64;
        const int s   = oc0 >> 8;                 // 0=q 1=k 2=v
        const int ch  = oc0 & (CC - 1);
        const int h   = ch >> 5;
        const int d0  = ch & (HD - 1);
        float4 bb = *(const float4*)(bq + oc0);
        float* dst = ((s == 0) ? g_q : (s == 1) ? g_k : g_v)
                   + (((size_t)b * NH + h) * TT) * HD + d0;
#pragma unroll
        for (int i = 0; i < 8; i++) {
            int t = t0 + tx * 4 + (i >> 2) * 64 + (i & 3);
            float4 o;
            o.x = acc[i][g * 4 + 0] + bb.x;
            o.y = acc[i][g * 4 + 1] + bb.y;
            o.z = acc[i][g * 4 + 2] + bb.z;
            o.w = acc[i][g * 4 + 3] + bb.w;
            *(float4*)(dst + (size_t)t * HD) = o;
        }
    }
}

// ---------------------------------------------------------------------------
// Kernel 3 (NEW): attention as two-phase smem-tiled GEMM per (b,h).
// 256 threads; dynamic smem.  Stage = 32 keys, 8 stages.
// Phase 1: S[32k][256q] = K_hat * Q_hat^T  (thread: 4k x 8q, d-reduction 32)
//          -> e = exp(S + bias - M) -> sP[k][q]
// Phase 2: out[256q][32d] += P^T V        (thread: 8q x 4d, k-reduction 32)
// q-tile per thread: {q0..q0+3} u {q0+128..q0+131},  q0 = (tid&31)*4.
// kg = dg = tid>>5 (4k in phase1, 4d in phase2).
// ---------------------------------------------------------------------------
#define AT_KS  32
#define QSTR   256
#define KSTR   36
#define SQ_OFF 0
#define SP_OFF (32 * QSTR)
#define SK_OFF (SP_OFF + AT_KS * QSTR)
#define SV_OFF (SK_OFF + 32 * KSTR)
#define IK_OFF (SV_OFF + AT_KS * KSTR)
#define ATT_SMEM ((IK_OFF + TT) * 4)

__global__ __launch_bounds__(256, 2) void attn_kernel(const float* __restrict__ tau)
{
    extern __shared__ float sm[];
    float* sQ  = sm + SQ_OFF;    // [32 d][256 q]
    float* sP  = sm + SP_OFF;    // [32 k][256 q]
    float* sK  = sm + SK_OFF;    // [32 d][36]   (k within stage, pre-scaled by ikn)
    float* sV  = sm + SV_OFF;    // [32 k][36]   (d)
    float* sIk = sm + IK_OFF;    // [256]

    const int tid = threadIdx.x;
    const int bh  = blockIdx.x;
    const int b   = bh >> 3;
    const int h   = bh & 7;
    const size_t base = (size_t)bh * TT * HD;
    const float inv_tau = 1.0f / fmaxf(tau[h], 0.01f);

    // ---- ikn table: one key row per thread
    {
        const float4* kr = (const float4*)(g_k + base + (size_t)tid * HD);
        float s2 = 0.0f;
#pragma unroll
        for (int i = 0; i < 8; i++) {
            float4 t4 = kr[i];
            s2 = fmaf(t4.x, t4.x, s2); s2 = fmaf(t4.y, t4.y, s2);
            s2 = fmaf(t4.z, t4.z, s2); s2 = fmaf(t4.w, t4.w, s2);
        }
        sIk[tid] = rsqrtf(fmaxf(s2, 1e-12f));
    }
    // ---- sQ: one query row per thread, normalized * inv_tau, transposed store
    {
        const float4* qr = (const float4*)(g_q + base + (size_t)tid * HD);
        float4 v[8];
        float s2 = 0.0f;
#pragma unroll
        for (int i = 0; i < 8; i++) {
            v[i] = qr[i];
            s2 = fmaf(v[i].x, v[i].x, s2); s2 = fmaf(v[i].y, v[i].y, s2);
            s2 = fmaf(v[i].z, v[i].z, s2); s2 = fmaf(v[i].w, v[i].w, s2);
        }
        float sc = rsqrtf(fmaxf(s2, 1e-12f)) * inv_tau;
#pragma unroll
        for (int i = 0; i < 8; i++) {
            sQ[(size_t)(4 * i + 0) * QSTR + tid] = v[i].x * sc;
            sQ[(size_t)(4 * i + 1) * QSTR + tid] = v[i].y * sc;
            sQ[(size_t)(4 * i + 2) * QSTR + tid] = v[i].z * sc;
            sQ[(size_t)(4 * i + 3) * QSTR + tid] = v[i].w * sc;
        }
    }

    const int qg = tid & 31;
    const int kg = tid >> 5;          // k-group in phase1, d-group in phase2
    const int q0 = qg * 4;

    float Mq[8];
    {
        float4 m0 = *(const float4*)(g_biasMax + h * TT + q0);
        float4 m1 = *(const float4*)(g_biasMax + h * TT + q0 + 128);
        Mq[0] = m0.x + inv_tau; Mq[1] = m0.y + inv_tau;
        Mq[2] = m0.z + inv_tau; Mq[3] = m0.w + inv_tau;
        Mq[4] = m1.x + inv_tau; Mq[5] = m1.y + inv_tau;
        Mq[6] = m1.z + inv_tau; Mq[7] = m1.w + inv_tau;
    }

    u64 o[4][4];                      // [q-pair][d]
    u64 lp[4];                        // l accumulators, q-pairs
#pragma unroll
    for (int i = 0; i < 4; i++) {
        lp[i] = 0ull;
#pragma unroll
        for (int j = 0; j < 4; j++) o[i][j] = 0ull;
    }

    __syncthreads();

    const float* bb = g_biasT + (size_t)h * TT * TT;

    for (int s = 0; s < TT / AT_KS; s++) {
        const int k0 = s * AT_KS;

        // ---- stage K (scaled) and V
        {
            int k  = tid >> 3;
            int d4 = tid & 7;
            float ik = sIk[k0 + k];
            float4 kv = *(const float4*)(g_k + base + (size_t)(k0 + k) * HD + d4 * 4);
            sK[(d4 * 4 + 0) * KSTR + k] = kv.x * ik;
            sK[(d4 * 4 + 1) * KSTR + k] = kv.y * ik;
            sK[(d4 * 4 + 2) * KSTR + k] = kv.z * ik;
            sK[(d4 * 4 + 3) * KSTR + k] = kv.w * ik;
            float4 vv = *(const float4*)(g_v + base + (size_t)(k0 + k) * HD + d4 * 4);
            *(float4*)(sV + k * KSTR + d4 * 4) = vv;
        }
        __syncthreads();

        // ---- phase 1: S[4k][8q]
        u64 S[4][4];
#pragma unroll
        for (int i = 0; i < 4; i++)
#pragma unroll
            for (int j = 0; j < 4; j++) S[i][j] = 0ull;

#pragma unroll 8
        for (int d = 0; d < HD; d++) {
            ulonglong2 qa = *(const ulonglong2*)(sQ + (size_t)d * QSTR + q0);
            ulonglong2 qb = *(const ulonglong2*)(sQ + (size_t)d * QSTR + q0 + 128);
            float4 kb = *(const float4*)(sK + d * KSTR + kg * 4);
            u64 kp0 = pack2(kb.x, kb.x);
            u64 kp1 = pack2(kb.y, kb.y);
            u64 kp2 = pack2(kb.z, kb.z);
            u64 kp3 = pack2(kb.w, kb.w);
            FMA2(S[0][0], qa.x, kp0); FMA2(S[0][1], qa.y, kp0);
            FMA2(S[0][2], qb.x, kp0); FMA2(S[0][3], qb.y, kp0);
            FMA2(S[1][0], qa.x, kp1); FMA2(S[1][1], qa.y, kp1);
            FMA2(S[1][2], qb.x, kp1); FMA2(S[1][3], qb.y, kp1);
            FMA2(S[2][0], qa.x, kp2); FMA2(S[2][1], qa.y, kp2);
            FMA2(S[2][2], qb.x, kp2); FMA2(S[2][3], qb.y, kp2);
            FMA2(S[3][0], qa.x, kp3); FMA2(S[3][1], qa.y, kp3);
            FMA2(S[3][2], qb.x, kp3); FMA2(S[3][3], qb.y, kp3);
        }

        // ---- bias + exp -> sP
#pragma unroll
        for (int kk = 0; kk < 4; kk++) {
            const float* br = bb + (size_t)(k0 + kg * 4 + kk) * TT;
            float4 blo = *(const float4*)(br + q0);
            float4 bhi = *(const float4*)(br + q0 + 128);
            float s0, s1, s2, s3, s4, s5, s6, s7;
            unpack2(S[kk][0], s0, s1);
            unpack2(S[kk][1], s2, s3);
            unpack2(S[kk][2], s4, s5);
            unpack2(S[kk][3], s6, s7);
            float4 elo, ehi;
            elo.x = __expf(s0 + (blo.x - Mq[0]));
            elo.y = __expf(s1 + (blo.y - Mq[1]));
            elo.z = __expf(s2 + (blo.z - Mq[2]));
            elo.w = __expf(s3 + (blo.w - Mq[3]));
            ehi.x = __expf(s4 + (bhi.x - Mq[4]));
            ehi.y = __expf(s5 + (bhi.y - Mq[5]));
            ehi.z = __expf(s6 + (bhi.z - Mq[6]));
            ehi.w = __expf(s7 + (bhi.w - Mq[7]));
            *(float4*)(sP + (size_t)(kg * 4 + kk) * QSTR + q0)       = elo;
            *(float4*)(sP + (size_t)(kg * 4 + kk) * QSTR + q0 + 128) = ehi;
        }
        __syncthreads();

        // ---- phase 2: out[8q][4d] += P^T V  (d0 = kg*4)
#pragma unroll 8
        for (int k = 0; k < AT_KS; k++) {
            ulonglong2 plo = *(const ulonglong2*)(sP + (size_t)k * QSTR + q0);
            ulonglong2 phi = *(const ulonglong2*)(sP + (size_t)k * QSTR + q0 + 128);
            float4 vv = *(const float4*)(sV + k * KSTR + kg * 4);
            ADD2(lp[0], plo.x); ADD2(lp[1], plo.y);
            ADD2(lp[2], phi.x); ADD2(lp[3], phi.y);
            u64 vp0 = pack2(vv.x, vv.x);
            u64 vp1 = pack2(vv.y, vv.y);
            u64 vp2 = pack2(vv.z, vv.z);
            u64 vp3 = pack2(vv.w, vv.w);
            FMA2(o[0][0], plo.x, vp0); FMA2(o[1][0], plo.y, vp0);
            FMA2(o[2][0], phi.x, vp0); FMA2(o[3][0], phi.y, vp0);
            FMA2(o[0][1], plo.x, vp1); FMA2(o[1][1], plo.y, vp1);
            FMA2(o[2][1], phi.x, vp1); FMA2(o[3][1], phi.y, vp1);
            FMA2(o[0][2], plo.x, vp2); FMA2(o[1][2], plo.y, vp2);
            FMA2(o[2][2], phi.x, vp2); FMA2(o[3][2], phi.y, vp2);
            FMA2(o[0][3], plo.x, vp3); FMA2(o[1][3], plo.y, vp3);
            FMA2(o[2][3], phi.x, vp3); FMA2(o[3][3], phi.y, vp3);
        }
        __syncthreads();
    }

    // ---- epilogue: divide by l, write g_ao[b][h*32+d][q]
    float il[8];
    {
        float l0, l1;
        unpack2(lp[0], l0, l1); il[0] = 1.0f / l0; il[1] = 1.0f / l1;
        unpack2(lp[1], l0, l1); il[2] = 1.0f / l0; il[3] = 1.0f / l1;
        unpack2(lp[2], l0, l1); il[4] = 1.0f / l0; il[5] = 1.0f / l1;
        unpack2(lp[3], l0, l1); il[6] = 1.0f / l0; il[7] = 1.0f / l1;
    }
#pragma unroll
    for (int d = 0; d < 4; d++) {
        float* row = g_ao + ((size_t)b * CC + h * HD + kg * 4 + d) * TT;
        float a, c;
        float4 olo, ohi;
        unpack2(o[0][d], a, c); olo.x = a * il[0]; olo.y = c * il[1];
        unpack2(o[1][d], a, c); olo.z = a * il[2]; olo.w = c * il[3];
        unpack2(o[2][d], a, c); ohi.x = a * il[4]; ohi.y = c * il[5];
        unpack2(o[3][d], a, c); ohi.z = a * il[6]; ohi.w = c * il[7];
        *(float4*)(row + q0)       = olo;
        *(float4*)(row + q0 + 128) = ohi;
    }
}

// ---------------------------------------------------------------------------
// Kernel 4: proj GEMM, FFMA2.  out[b,co,t] = sum_ci ao[b,ci,t]*w[co,ci]+b[co]
// ---------------------------------------------------------------------------
__global__ __launch_bounds__(256, 2) void proj_kernel(
    const float* __restrict__ w, const float* __restrict__ bp,
    float* __restrict__ out)
{
    __shared__ float As[GBK * GBM];
    __shared__ float Bs[GBK * BNP];

    const int tid = threadIdx.x;
    const int tx = tid & 15;
    const int ty = tid >> 4;
    const int m0 = blockIdx.y * GBM;
    const int n0 = blockIdx.x * GBN;
    const int b  = m0 >> 8;
    const int t0 = m0 & (TT - 1);
    const float* ab = g_ao + (size_t)b * CC * TT;

    u64 acc_p[4][8];
#pragma unroll
    for (int i = 0; i < 4; i++)
#pragma unroll
        for (int j = 0; j < 8; j++) acc_p[i][j] = 0ull;

    for (int k0 = 0; k0 < CC; k0 += GBK) {
#pragma unroll
        for (int s = 0; s < 2; s++) {
            int item = tid + s * 256;
            int kk = item >> 5;
            int t4 = item & 31;
            float4 v4 = *(const float4*)(ab + (size_t)(k0 + kk) * TT + t0 + t4 * 4);
            *(float4*)(As + kk * GBM + t4 * 4) = v4;
        }
#pragma unroll
        for (int s = 0; s < 2; s++) {
            int item = tid + s * 256;
            int n  = item >> 2;
            int kq = item & 3;
            float4 v4 = *(const float4*)(w + (size_t)(n0 + n) * CC + k0 + kq * 4);
            Bs[(kq * 4 + 0) * BNP + n] = v4.x;
            Bs[(kq * 4 + 1) * BNP + n] = v4.y;
            Bs[(kq * 4 + 2) * BNP + n] = v4.z;
            Bs[(kq * 4 + 3) * BNP + n] = v4.w;
        }
        __syncthreads();

#pragma unroll
        for (int k = 0; k < GBK; k++) {
            const float* arow = As + k * GBM + tx * 4;
            ulonglong2 aa0 = *(const ulonglong2*)(arow);
            ulonglong2 aa1 = *(const ulonglong2*)(arow + 64);
            float4 b0 = *(const float4*)(Bs + k * BNP + ty * 4);
            float4 b1 = *(const float4*)(Bs + k * BNP + ty * 4 + 64);
            u64 bb[8];
            bb[0] = pack2(b0.x, b0.x); bb[1] = pack2(b0.y, b0.y);
            bb[2] = pack2(b0.z, b0.z); bb[3] = pack2(b0.w, b0.w);
            bb[4] = pack2(b1.x, b1.x); bb[5] = pack2(b1.y, b1.y);
            bb[6] = pack2(b1.z, b1.z); bb[7] = pack2(b1.w, b1.w);
#pragma unroll
            for (int j = 0; j < 8; j++) {
                FMA2(acc_p[0][j], aa0.x, bb[j]);
                FMA2(acc_p[1][j], aa0.y, bb[j]);
                FMA2(acc_p[2][j], aa1.x, bb[j]);
                FMA2(acc_p[3][j], aa1.y, bb[j]);
            }
        }
        __syncthreads();
    }

    float acc[8][8];
#pragma unroll
    for (int i2 = 0; i2 < 4; i2++)
#pragma unroll
        for (int j = 0; j < 8; j++) {
            float lo, hi;
            unpack2(acc_p[i2][j], lo, hi);
            acc[2 * i2][j] = lo;
            acc[2 * i2 + 1][j] = hi;
        }

#pragma unroll
    for (int g = 0; g < 2; g++) {
#pragma unroll
        for (int j = 0; j < 4; j++) {
            int n = n0 + ty * 4 + g * 64 + j;
            float bpv = bp[n];
            float4 oo;
            oo.x = acc[0][g*4+j] + bpv;
            oo.y = acc[1][g*4+j] + bpv;
            oo.z = acc[2][g*4+j] + bpv;
            oo.w = acc[3][g*4+j] + bpv;
            *(float4*)(out + ((size_t)b * CC + n) * TT + t0 + tx * 4) = oo;
            oo.x = acc[4][g*4+j] + bpv;
            oo.y = acc[5][g*4+j] + bpv;
            oo.z = acc[6][g*4+j] + bpv;
            oo.w = acc[7][g*4+j] + bpv;
            *(float4*)(out + ((size_t)b * CC + n) * TT + t0 + tx * 4 + 64) = oo;
        }
    }
}

// ---------------------------------------------------------------------------
extern "C" void kernel_launch(void* const* d_in, const int* in_sizes, int n_in,
                              void* d_out, int out_size)
{
    const float* x      = (const float*)d_in[0];
    const float* w_qkv  = (const float*)d_in[1];
    const float* b_qkv  = (const float*)d_in[2];
    const float* w_proj = (const float*)d_in[3];
    const float* b_proj = (const float*)d_in[4];
    const float* mw1    = (const float*)d_in[5];
    const float* mb1    = (const float*)d_in[6];
    const float* mw2    = (const float*)d_in[7];
    const float* mb2    = (const float*)d_in[8];
    const float* tau    = (const float*)d_in[9];
    float* out = (float*)d_out;

    cudaFuncSetAttribute(attn_kernel,
                         cudaFuncAttributeMaxDynamicSharedMemorySize, ATT_SMEM);

    bias_kernel<<<TT * TT / 256, 256>>>(mw1, mb1, mw2, mb2);
    biasmax_kernel<<<NH, 256>>>();
    qkv_kernel<<<dim3(OC3 / GBN, BB * TT / GBM), 256>>>(x, w_qkv, b_qkv);
    attn_kernel<<<BB * NH, 256, ATT_SMEM>>>(tau);
    proj_kernel<<<dim3(CC / GBN, BB * TT / GBM), 256>>>(w_proj, b_proj, out);
}